// round 4
// baseline (speedup 1.0000x reference)
#include <cuda_runtime.h>
#include <cstdint>

typedef unsigned long long ull;

#define BATCH 8192
#define HID 128
#define TSTEPS 64
#define NCTA 128      // 8192 / 64 rows per CTA
#define RPC 64        // rows per CTA
#define THREADS 512

constexpr int KC = 16;          // k-chunk for streamed weights
constexpr int NCH = 128 / KC;   // 8 chunks

// ---------------- scratch (device globals; no allocations allowed) ----------
__device__ float g_x2[BATCH * HID];
__device__ float g_zc[BATCH * HID];

// ---------------- smem layout (float offsets) --------------------------------
constexpr int OFF_H0 = 0;            // h ping  [k=128][row=64]
constexpr int OFF_H1 = 8192;         // h pong
constexpr int OFF_B  = 16384;        // biases: enc 768 (ih|hh) + dec 768
constexpr int OFF_RB = 17920;        // union region:
// enc: Wih^T [29][384] (11136) | x_t [29][64->2048] | 2 chunk bufs [16][384] (6144 ea)
// dec: 2 chunk bufs [16][768] (12288 ea)
// heads: dis_w+value_w [79][256] (20224) | h transposed [64][128] (8192)
constexpr int RB_SIZE = 28416;
constexpr int SM_FLOATS = OFF_RB + RB_SIZE;        // 46336
constexpr int SMEM_BYTES = SM_FLOATS * 4;          // 185344

constexpr int E_WI = 0;          // within RB
constexpr int E_X  = 11136;
constexpr int E_C0 = 13184;
constexpr int E_C1 = 19328;
constexpr int D_C0 = 0;
constexpr int D_C1 = 12288;
constexpr int H_DW = 0;
constexpr int H_HT = 20224;

constexpr int CONV_SMEM = (16 * 1728 + 3888 + 2048 + 16 * 144) * 4;

// ---------------- packed f32x2 helpers --------------------------------------
__device__ __forceinline__ ull pk2(float a, float b) {
    ull r; asm("mov.b64 %0, {%1,%2};" : "=l"(r) : "f"(a), "f"(b)); return r;
}
__device__ __forceinline__ void upk2(ull v, float& a, float& b) {
    asm("mov.b64 {%0,%1}, %2;" : "=f"(a), "=f"(b) : "l"(v));
}
__device__ __forceinline__ void fma2(ull& d, ull a, ull b) {
    asm("fma.rn.f32x2 %0, %1, %2, %0;" : "+l"(d) : "l"(a), "l"(b));
}
__device__ __forceinline__ float sigf(float x)     { return 1.0f / (1.0f + __expf(-x)); }
__device__ __forceinline__ float tanhfast(float x) { return 2.0f / (1.0f + __expf(-2.0f * x)) - 1.0f; }

// ---------------- GEMM fragment ----------------------------------------------
// acc[s][rr] for sections SB..SE-1, 4 rows. W cols at (s-CS)*128 + col0, width WW.
// Operand sOp layout [k][64 rows].
template <int WW, int SB, int SE, int CS, int KN>
__device__ __forceinline__ void frag(const float* __restrict__ sW,
                                     const float* __restrict__ sOp,
                                     ull (&acc)[6][4], int col0, int prow)
{
#pragma unroll
    for (int k = 0; k < KN; ++k) {
        float4 hv = *(const float4*)(sOp + k * 64 + prow);
        ull h0 = pk2(hv.x, hv.x), h1 = pk2(hv.y, hv.y);
        ull h2 = pk2(hv.z, hv.z), h3 = pk2(hv.w, hv.w);
#pragma unroll
        for (int s = SB; s < SE; ++s) {
            ull wv = *(const ull*)(sW + k * WW + (s - CS) * 128 + col0);
            fma2(acc[s][0], h0, wv); fma2(acc[s][1], h1, wv);
            fma2(acc[s][2], h2, wv); fma2(acc[s][3], h3, wv);
        }
    }
}

// ---------------- chunk staging ----------------------------------------------
// dec: 768 cols (0..383 = Wih rows, 384..767 = Whh rows), 16 k -> 12288 floats.
__device__ __forceinline__ void ldg_dec(float4 st[6], const float* __restrict__ Wih,
                                        const float* __restrict__ Whh, int kb)
{
#pragma unroll
    for (int i = 0; i < 6; ++i) {
        int e = threadIdx.x + i * THREADS;    // 0..3071
        int j = e >> 2, kq = e & 3;
        const float* src = (j < 384 ? Wih + (size_t)j * 128
                                    : Whh + (size_t)(j - 384) * 128) + kb + kq * 4;
        st[i] = *(const float4*)src;
    }
}
__device__ __forceinline__ void sts_dec(const float4 st[6], float* __restrict__ buf)
{
#pragma unroll
    for (int i = 0; i < 6; ++i) {
        int e = threadIdx.x + i * THREADS;
        int j = e >> 2, kq = e & 3;
        buf[(kq * 4 + 0) * 768 + j] = st[i].x;
        buf[(kq * 4 + 1) * 768 + j] = st[i].y;
        buf[(kq * 4 + 2) * 768 + j] = st[i].z;
        buf[(kq * 4 + 3) * 768 + j] = st[i].w;
    }
}
// enc h-chunk: 384 cols (Whh), 16 k -> 6144 floats.
__device__ __forceinline__ void ldg_enc(float4 st[3], const float* __restrict__ Whh, int kb)
{
#pragma unroll
    for (int i = 0; i < 3; ++i) {
        int e = threadIdx.x + i * THREADS;    // 0..1535
        int j = e >> 2, kq = e & 3;
        st[i] = *(const float4*)(Whh + (size_t)j * 128 + kb + kq * 4);
    }
}
__device__ __forceinline__ void sts_enc(const float4 st[3], float* __restrict__ buf)
{
#pragma unroll
    for (int i = 0; i < 3; ++i) {
        int e = threadIdx.x + i * THREADS;
        int j = e >> 2, kq = e & 3;
        buf[(kq * 4 + 0) * 384 + j] = st[i].x;
        buf[(kq * 4 + 1) * 384 + j] = st[i].y;
        buf[(kq * 4 + 2) * 384 + j] = st[i].z;
        buf[(kq * 4 + 3) * 384 + j] = st[i].w;
    }
}

// ---------------- GRU epilogue -------------------------------------------------
__device__ __forceinline__ void gru_epi(ull (&acc)[6][4], const float* __restrict__ hc,
                                        float* __restrict__ hn, int j, int prow)
{
#pragma unroll
    for (int rr = 0; rr < 4; ++rr) {
        int r = prow + rr;
        float xr0, xr1, xz0, xz1, xn0, xn1, hr0, hr1, hz0, hz1, hn0, hn1;
        upk2(acc[0][rr], xr0, xr1); upk2(acc[1][rr], xz0, xz1); upk2(acc[2][rr], xn0, xn1);
        upk2(acc[3][rr], hr0, hr1); upk2(acc[4][rr], hz0, hz1); upk2(acc[5][rr], hn0, hn1);
        float rg0 = sigf(xr0 + hr0), rg1 = sigf(xr1 + hr1);
        float z0  = sigf(xz0 + hz0), z1  = sigf(xz1 + hz1);
        float n0  = tanhfast(xn0 + rg0 * hn0), n1 = tanhfast(xn1 + rg1 * hn1);
        float hp0 = hc[j * 64 + r], hp1 = hc[(j + 1) * 64 + r];
        hn[j * 64 + r]       = (1.0f - z0) * n0 + z0 * hp0;
        hn[(j + 1) * 64 + r] = (1.0f - z1) * n1 + z1 * hp1;
    }
}

// =============================================================================
// Persistent recurrence kernel: each CTA owns 64 batch rows for the whole
// enc(64 steps) + dec(64 steps) + heads. h lives in smem the entire time.
// =============================================================================
__global__ void __launch_bounds__(THREADS, 1)
recur_k(const float* __restrict__ lin,
        const float* __restrict__ eWih, const float* __restrict__ eWhh,
        const float* __restrict__ ebih, const float* __restrict__ ebhh,
        const float* __restrict__ dWih, const float* __restrict__ dWhh,
        const float* __restrict__ dbih, const float* __restrict__ dbhh,
        const float* __restrict__ disw, const float* __restrict__ disb,
        const float* __restrict__ vw,   const float* __restrict__ vb,
        float* __restrict__ out)
{
    extern __shared__ float sm[];
    float* sB  = sm + OFF_B;
    float* sRB = sm + OFF_RB;

    const int tid   = threadIdx.x;
    const int rb    = blockIdx.x * RPC;
    const int fslot = tid >> 3;          // 0..63  (feature pair)
    const int rg    = tid & 7;           // 0..7   (row group of 4)
    const int col0  = 2 * fslot;
    const int j     = col0;

    // init: zero h0, stage biases, stage enc Wih^T [k=29][384]
    for (int i = tid; i < 8192; i += THREADS) sm[OFF_H0 + i] = 0.0f;
    for (int i = tid; i < 384; i += THREADS) {
        sB[i]        = ebih[i];  sB[384 + i]  = ebhh[i];
        sB[768 + i]  = dbih[i];  sB[1152 + i] = dbhh[i];
    }
    for (int i = tid; i < 29 * 384; i += THREADS) {
        int k = i / 384, jj = i % 384;
        sRB[E_WI + i] = eWih[(size_t)jj * 29 + k];
    }
    __syncthreads();

    int cur = 0;

    // ===================== encoder =====================
    {
        float* sX   = sRB + E_X;
        float* bufs[2] = { sRB + E_C0, sRB + E_C1 };
        float4 st[3];
        ldg_enc(st, eWhh, 0);   // prologue chunk 0

        for (int t = 0; t < TSTEPS; ++t) {
            float* hc = sm + (cur ? OFF_H1 : OFF_H0);
            float* hn = sm + (cur ? OFF_H0 : OFF_H1);
            // stage x_t transposed [k][64]
            for (int i = tid; i < 64 * 29; i += THREADS) {
                int r = i / 29, k = i % 29;
                sX[k * 64 + r] = lin[(size_t)(rb + r) * (TSTEPS * 29) + (size_t)t * 29 + k];
            }
            __syncthreads();

            for (int pass = 0; pass < 2; ++pass) {
                const int prow = pass * 32 + rg * 4;
                ull acc[6][4];
#pragma unroll
                for (int s = 0; s < 6; ++s) {
                    ull bv = *(const ull*)(sB + s * 128 + col0);
#pragma unroll
                    for (int rr = 0; rr < 4; ++rr) acc[s][rr] = bv;
                }
                // x-part: sections 0..2, K=29, Wih persistent
                frag<384, 0, 3, 0, 29>(sRB + E_WI, sX, acc, col0, prow);
                // h-part: sections 3..5, K=128 streamed in 8 chunks
                for (int kc = 0; kc < NCH; ++kc) {
                    float* buf = bufs[kc & 1];
                    sts_enc(st, buf);
                    __syncthreads();
                    ldg_enc(st, eWhh, ((kc + 1) & (NCH - 1)) * KC);  // next (wraps: same W every pass/step)
                    frag<384, 3, 6, 3, KC>(buf, hc + kc * KC * 64, acc, col0, prow);
                    __syncthreads();
                }
                gru_epi(acc, hc, hn, j, prow);
            }
            __syncthreads();
            cur ^= 1;
        }
    }

    // ===================== decoder =====================
    {
        float* bufs[2] = { sRB + D_C0, sRB + D_C1 };
        float4 st[6];
        ldg_dec(st, dWih, dWhh, 0);
        __syncthreads();   // enc-region readers done before dec STS overwrites RB

        for (int t = 0; t < TSTEPS; ++t) {
            float* hc = sm + (cur ? OFF_H1 : OFF_H0);
            float* hn = sm + (cur ? OFF_H0 : OFF_H1);

            for (int pass = 0; pass < 2; ++pass) {
                const int prow = pass * 32 + rg * 4;
                ull acc[6][4];
#pragma unroll
                for (int s = 0; s < 6; ++s) {
                    ull bv = *(const ull*)(sB + 768 + s * 128 + col0);
#pragma unroll
                    for (int rr = 0; rr < 4; ++rr) acc[s][rr] = bv;
                }
                for (int kc = 0; kc < NCH; ++kc) {
                    float* buf = bufs[kc & 1];
                    sts_dec(st, buf);
                    __syncthreads();
                    ldg_dec(st, dWih, dWhh, ((kc + 1) & (NCH - 1)) * KC);
                    const float* op = hc + kc * KC * 64;
                    if (t == 0)  // xin = 0: gx = bih only, skip sections 0..2
                        frag<768, 3, 6, 0, KC>(buf, op, acc, col0, prow);
                    else         // xin == h: all 6 sections share operand h
                        frag<768, 0, 6, 0, KC>(buf, op, acc, col0, prow);
                    __syncthreads();
                }
                gru_epi(acc, hc, hn, j, prow);
            }
            __syncthreads();
            cur ^= 1;
        }
    }

    // ===================== heads =====================
    {
        float* hfin = sm + (cur ? OFF_H1 : OFF_H0);
        float* zb   = sm + (cur ? OFF_H0 : OFF_H1);   // reuse pong for z_cnn rows
        float* sDW  = sRB + H_DW;                     // [79][256]
        float* sHT  = sRB + H_HT;                     // h transposed [r][128]

        for (int i = tid; i < 64 * 128; i += THREADS) zb[i] = g_zc[(size_t)rb * 128 + i];
        for (int i = tid; i < 79 * 256; i += THREADS)
            sDW[i] = (i < 78 * 256) ? disw[i] : vw[i - 78 * 256];
        for (int i = tid; i < 64 * 128; i += THREADS) {
            int r = i >> 7, k = i & 127;
            sHT[i] = hfin[k * 64 + r];
        }
        __syncthreads();

        for (int o = tid; o < 64 * 79; o += THREADS) {
            int r = o / 79, c = o % 79;
            const ull* wp = (const ull*)(sDW + c * 256);
            const ull* zr = (const ull*)(zb + r * 128);
            const ull* hr = (const ull*)(sHT + r * 128);
            ull a2 = pk2(0.0f, 0.0f);
#pragma unroll 8
            for (int k = 0; k < 64; ++k) fma2(a2, zr[k], wp[k]);
#pragma unroll 8
            for (int k = 0; k < 64; ++k) fma2(a2, hr[k], wp[64 + k]);
            float lo, hi; upk2(a2, lo, hi);
            float acc = ((c < 78) ? disb[c] : vb[0]) + lo + hi;
            if (c < 78) out[(size_t)(rb + r) * 78 + c] = acc;
            else        out[(size_t)BATCH * 78 + rb + r] = acc;
        }
    }
}

// =============================================================================
// CNN: conv1 (27->16, 3x3, s2) + relu + conv2 (16->32, 2x2, s1) + relu
// =============================================================================
__global__ void __launch_bounds__(256, 1)
conv_k(const float* __restrict__ cnn,
       const float* __restrict__ w1, const float* __restrict__ b1,
       const float* __restrict__ w2, const float* __restrict__ b2)
{
    extern __shared__ float sms[];
    float* sin_ = sms;
    float* sw1  = sin_ + 16 * 1728;
    float* sw2  = sw1 + 3888;
    float* sx1  = sw2 + 2048;

    const int tid = threadIdx.x;
    const int b0  = blockIdx.x * 16;

    for (int i = tid; i < 16 * 1728; i += 256) sin_[i] = cnn[(size_t)b0 * 1728 + i];
    for (int i = tid; i < 3888; i += 256) sw1[i] = w1[i];
    for (int i = tid; i < 2048; i += 256) sw2[i] = w2[i];
    __syncthreads();

    const int bb = tid >> 4;
    const int c  = tid & 15;

    float acc[9];
    float bc = b1[c];
#pragma unroll
    for (int p = 0; p < 9; ++p) acc[p] = bc;
    for (int ky = 0; ky < 3; ++ky)
        for (int kx = 0; kx < 3; ++kx)
            for (int ic = 0; ic < 27; ++ic) {
                float w = sw1[c * 243 + ic * 9 + ky * 3 + kx];
#pragma unroll
                for (int i = 0; i < 3; ++i)
#pragma unroll
                    for (int jx = 0; jx < 3; ++jx)
                        acc[i * 3 + jx] = fmaf(sin_[((bb * 8 + 2 * i + ky) * 8 + 2 * jx + kx) * 27 + ic],
                                               w, acc[i * 3 + jx]);
            }
#pragma unroll
    for (int p = 0; p < 9; ++p) sx1[(bb * 16 + c) * 9 + p] = fmaxf(acc[p], 0.0f);
    __syncthreads();

    float a2[2][4];
#pragma unroll
    for (int q = 0; q < 2; ++q) {
        float bcc = b2[c + 16 * q];
#pragma unroll
        for (int p = 0; p < 4; ++p) a2[q][p] = bcc;
    }
    for (int ci = 0; ci < 16; ++ci) {
        float xv[9];
#pragma unroll
        for (int p = 0; p < 9; ++p) xv[p] = sx1[(bb * 16 + ci) * 9 + p];
#pragma unroll
        for (int q = 0; q < 2; ++q) {
            int c2 = c + 16 * q;
#pragma unroll
            for (int ky = 0; ky < 2; ++ky)
#pragma unroll
                for (int kx = 0; kx < 2; ++kx) {
                    float w = sw2[(c2 * 16 + ci) * 4 + ky * 2 + kx];
#pragma unroll
                    for (int i = 0; i < 2; ++i)
#pragma unroll
                        for (int jx = 0; jx < 2; ++jx)
                            a2[q][i * 2 + jx] = fmaf(xv[(i + ky) * 3 + (jx + kx)], w, a2[q][i * 2 + jx]);
                }
        }
    }
    float* outp = g_x2 + (size_t)(b0 + bb) * 128;
#pragma unroll
    for (int q = 0; q < 2; ++q)
#pragma unroll
        for (int p = 0; p < 4; ++p)
            outp[(c + 16 * q) * 4 + p] = fmaxf(a2[q][p], 0.0f);
}

// fc: z_cnn = relu(g_x2 @ fc_w^T + fc_b)
__global__ void fc_k(const float* __restrict__ W, const float* __restrict__ bias)
{
    int gid = blockIdx.x * 256 + threadIdx.x;
    int b = gid >> 7, jj = gid & 127;
    const float* xr = g_x2 + (size_t)b * 128;
    const float* wr = W + (size_t)jj * 128;
    float acc = bias[jj];
#pragma unroll 8
    for (int k = 0; k < 128; ++k) acc = fmaf(xr[k], wr[k], acc);
    g_zc[gid] = fmaxf(acc, 0.0f);
}

// =============================================================================
extern "C" void kernel_launch(void* const* d_in, const int* in_sizes, int n_in,
                              void* d_out, int out_size)
{
    const float* cnn  = (const float*)d_in[0];
    const float* lin  = (const float*)d_in[1];
    const float* c1w  = (const float*)d_in[2];
    const float* c1b  = (const float*)d_in[3];
    const float* c2w  = (const float*)d_in[4];
    const float* c2b  = (const float*)d_in[5];
    const float* fcw  = (const float*)d_in[6];
    const float* fcb  = (const float*)d_in[7];
    const float* eWih = (const float*)d_in[8];
    const float* eWhh = (const float*)d_in[9];
    const float* ebih = (const float*)d_in[10];
    const float* ebhh = (const float*)d_in[11];
    const float* dWih = (const float*)d_in[12];
    const float* dWhh = (const float*)d_in[13];
    const float* dbih = (const float*)d_in[14];
    const float* dbhh = (const float*)d_in[15];
    const float* disw = (const float*)d_in[16];
    const float* disb = (const float*)d_in[17];
    const float* vw   = (const float*)d_in[18];
    const float* vb   = (const float*)d_in[19];
    float* out = (float*)d_out;

    cudaFuncSetAttribute(conv_k,  cudaFuncAttributeMaxDynamicSharedMemorySize, CONV_SMEM);
    cudaFuncSetAttribute(recur_k, cudaFuncAttributeMaxDynamicSharedMemorySize, SMEM_BYTES);

    conv_k<<<BATCH / 16, 256, CONV_SMEM>>>(cnn, c1w, c1b, c2w, c2b);
    fc_k<<<BATCH * 128 / 256, 256>>>(fcw, fcb);

    recur_k<<<NCTA, THREADS, SMEM_BYTES>>>(lin,
                                           eWih, eWhh, ebih, ebhh,
                                           dWih, dWhh, dbih, dbhh,
                                           disw, disb, vw, vb, out);
}

// round 5
// speedup vs baseline: 1.0012x; 1.0012x over previous
#include <cuda_runtime.h>
#include <cstdint>

typedef unsigned long long ull;

#define BATCH 8192
#define HID 128
#define TSTEPS 64
#define NCTA 128      // 8192 / 64 rows per CTA
#define RPC 64        // rows per CTA
#define THREADS 512

constexpr int KC = 16;          // k-chunk for streamed weights
constexpr int NCH = 128 / KC;   // 8 chunks

// ---------------- scratch (device globals; no allocations allowed) ----------
__device__ float g_x2[BATCH * HID];
__device__ float g_zc[BATCH * HID];

// ---------------- smem layout (float offsets) --------------------------------
constexpr int OFF_H0 = 0;            // h ping  [k=128][row=64]
constexpr int OFF_H1 = 8192;         // h pong
constexpr int OFF_B  = 16384;        // biases: enc 768 (ih|hh) + dec 768
constexpr int OFF_RB = 17920;        // union region:
// enc: Wih^T [29][384] (11136) | x_t [29][64->2048] | 2 chunk bufs [16][384] (6144 ea)
// dec: 2 chunk bufs [16][768] (12288 ea)
// heads: dis_w+value_w [79][256] (20224) | h transposed [64][128] (8192)
constexpr int RB_SIZE = 28416;
constexpr int SM_FLOATS = OFF_RB + RB_SIZE;        // 46336
constexpr int SMEM_BYTES = SM_FLOATS * 4;          // 185344

constexpr int E_WI = 0;          // within RB
constexpr int E_X  = 11136;
constexpr int E_C0 = 13184;
constexpr int E_C1 = 19328;
constexpr int D_C0 = 0;
constexpr int D_C1 = 12288;
constexpr int H_DW = 0;
constexpr int H_HT = 20224;

constexpr int CONV_SMEM = (16 * 1728 + 3888 + 2048 + 16 * 144) * 4;

// ---------------- packed f32x2 helpers --------------------------------------
__device__ __forceinline__ ull pk2(float a, float b) {
    ull r; asm("mov.b64 %0, {%1,%2};" : "=l"(r) : "f"(a), "f"(b)); return r;
}
__device__ __forceinline__ void upk2(ull v, float& a, float& b) {
    asm("mov.b64 {%0,%1}, %2;" : "=f"(a), "=f"(b) : "l"(v));
}
__device__ __forceinline__ void fma2(ull& d, ull a, ull b) {
    asm("fma.rn.f32x2 %0, %1, %2, %0;" : "+l"(d) : "l"(a), "l"(b));
}
__device__ __forceinline__ float sigf(float x)     { return 1.0f / (1.0f + __expf(-x)); }
__device__ __forceinline__ float tanhfast(float x) { return 2.0f / (1.0f + __expf(-2.0f * x)) - 1.0f; }

// ---------------- GEMM fragment ----------------------------------------------
// acc[s][rr] for sections SB..SE-1, 4 rows. W cols at (s-CS)*128 + col0, width WW.
// Operand sOp layout [k][64 rows].
template <int WW, int SB, int SE, int CS, int KN>
__device__ __forceinline__ void frag(const float* __restrict__ sW,
                                     const float* __restrict__ sOp,
                                     ull (&acc)[6][4], int col0, int prow)
{
#pragma unroll
    for (int k = 0; k < KN; ++k) {
        float4 hv = *(const float4*)(sOp + k * 64 + prow);
        ull h0 = pk2(hv.x, hv.x), h1 = pk2(hv.y, hv.y);
        ull h2 = pk2(hv.z, hv.z), h3 = pk2(hv.w, hv.w);
#pragma unroll
        for (int s = SB; s < SE; ++s) {
            ull wv = *(const ull*)(sW + k * WW + (s - CS) * 128 + col0);
            fma2(acc[s][0], h0, wv); fma2(acc[s][1], h1, wv);
            fma2(acc[s][2], h2, wv); fma2(acc[s][3], h3, wv);
        }
    }
}

// ---------------- chunk staging ----------------------------------------------
// dec: 768 cols (0..383 = Wih rows, 384..767 = Whh rows), 16 k -> 12288 floats.
__device__ __forceinline__ void ldg_dec(float4 st[6], const float* __restrict__ Wih,
                                        const float* __restrict__ Whh, int kb)
{
#pragma unroll
    for (int i = 0; i < 6; ++i) {
        int e = threadIdx.x + i * THREADS;    // 0..3071
        int j = e >> 2, kq = e & 3;
        const float* src = (j < 384 ? Wih + (size_t)j * 128
                                    : Whh + (size_t)(j - 384) * 128) + kb + kq * 4;
        st[i] = *(const float4*)src;
    }
}
__device__ __forceinline__ void sts_dec(const float4 st[6], float* __restrict__ buf)
{
#pragma unroll
    for (int i = 0; i < 6; ++i) {
        int e = threadIdx.x + i * THREADS;
        int j = e >> 2, kq = e & 3;
        buf[(kq * 4 + 0) * 768 + j] = st[i].x;
        buf[(kq * 4 + 1) * 768 + j] = st[i].y;
        buf[(kq * 4 + 2) * 768 + j] = st[i].z;
        buf[(kq * 4 + 3) * 768 + j] = st[i].w;
    }
}
// enc h-chunk: 384 cols (Whh), 16 k -> 6144 floats.
__device__ __forceinline__ void ldg_enc(float4 st[3], const float* __restrict__ Whh, int kb)
{
#pragma unroll
    for (int i = 0; i < 3; ++i) {
        int e = threadIdx.x + i * THREADS;    // 0..1535
        int j = e >> 2, kq = e & 3;
        st[i] = *(const float4*)(Whh + (size_t)j * 128 + kb + kq * 4);
    }
}
__device__ __forceinline__ void sts_enc(const float4 st[3], float* __restrict__ buf)
{
#pragma unroll
    for (int i = 0; i < 3; ++i) {
        int e = threadIdx.x + i * THREADS;
        int j = e >> 2, kq = e & 3;
        buf[(kq * 4 + 0) * 384 + j] = st[i].x;
        buf[(kq * 4 + 1) * 384 + j] = st[i].y;
        buf[(kq * 4 + 2) * 384 + j] = st[i].z;
        buf[(kq * 4 + 3) * 384 + j] = st[i].w;
    }
}

// ---------------- GRU epilogue -------------------------------------------------
__device__ __forceinline__ void gru_epi(ull (&acc)[6][4], const float* __restrict__ hc,
                                        float* __restrict__ hn, int j, int prow)
{
#pragma unroll
    for (int rr = 0; rr < 4; ++rr) {
        int r = prow + rr;
        float xr0, xr1, xz0, xz1, xn0, xn1, hr0, hr1, hz0, hz1, hn0, hn1;
        upk2(acc[0][rr], xr0, xr1); upk2(acc[1][rr], xz0, xz1); upk2(acc[2][rr], xn0, xn1);
        upk2(acc[3][rr], hr0, hr1); upk2(acc[4][rr], hz0, hz1); upk2(acc[5][rr], hn0, hn1);
        float rg0 = sigf(xr0 + hr0), rg1 = sigf(xr1 + hr1);
        float z0  = sigf(xz0 + hz0), z1  = sigf(xz1 + hz1);
        float n0  = tanhfast(xn0 + rg0 * hn0), n1 = tanhfast(xn1 + rg1 * hn1);
        float hp0 = hc[j * 64 + r], hp1 = hc[(j + 1) * 64 + r];
        hn[j * 64 + r]       = (1.0f - z0) * n0 + z0 * hp0;
        hn[(j + 1) * 64 + r] = (1.0f - z1) * n1 + z1 * hp1;
    }
}

// =============================================================================
// Persistent recurrence kernel: each CTA owns 64 batch rows for the whole
// enc(64 steps) + dec(64 steps) + heads. h lives in smem the entire time.
// =============================================================================
__global__ void __launch_bounds__(THREADS, 1)
recur_k(const float* __restrict__ lin,
        const float* __restrict__ eWih, const float* __restrict__ eWhh,
        const float* __restrict__ ebih, const float* __restrict__ ebhh,
        const float* __restrict__ dWih, const float* __restrict__ dWhh,
        const float* __restrict__ dbih, const float* __restrict__ dbhh,
        const float* __restrict__ disw, const float* __restrict__ disb,
        const float* __restrict__ vw,   const float* __restrict__ vb,
        float* __restrict__ out)
{
    extern __shared__ float sm[];
    float* sB  = sm + OFF_B;
    float* sRB = sm + OFF_RB;

    const int tid   = threadIdx.x;
    const int rb    = blockIdx.x * RPC;
    const int fslot = tid >> 3;          // 0..63  (feature pair)
    const int rg    = tid & 7;           // 0..7   (row group of 4)
    const int col0  = 2 * fslot;
    const int j     = col0;

    // init: zero h0, stage biases, stage enc Wih^T [k=29][384]
    for (int i = tid; i < 8192; i += THREADS) sm[OFF_H0 + i] = 0.0f;
    for (int i = tid; i < 384; i += THREADS) {
        sB[i]        = ebih[i];  sB[384 + i]  = ebhh[i];
        sB[768 + i]  = dbih[i];  sB[1152 + i] = dbhh[i];
    }
    for (int i = tid; i < 29 * 384; i += THREADS) {
        int k = i / 384, jj = i % 384;
        sRB[E_WI + i] = eWih[(size_t)jj * 29 + k];
    }
    __syncthreads();

    int cur = 0;

    // ===================== encoder =====================
    {
        float* sX   = sRB + E_X;
        float* bufs[2] = { sRB + E_C0, sRB + E_C1 };
        float4 st[3];
        ldg_enc(st, eWhh, 0);   // prologue chunk 0

        for (int t = 0; t < TSTEPS; ++t) {
            float* hc = sm + (cur ? OFF_H1 : OFF_H0);
            float* hn = sm + (cur ? OFF_H0 : OFF_H1);
            // stage x_t transposed [k][64]
            for (int i = tid; i < 64 * 29; i += THREADS) {
                int r = i / 29, k = i % 29;
                sX[k * 64 + r] = lin[(size_t)(rb + r) * (TSTEPS * 29) + (size_t)t * 29 + k];
            }
            __syncthreads();

            for (int pass = 0; pass < 2; ++pass) {
                const int prow = pass * 32 + rg * 4;
                ull acc[6][4];
#pragma unroll
                for (int s = 0; s < 6; ++s) {
                    ull bv = *(const ull*)(sB + s * 128 + col0);
#pragma unroll
                    for (int rr = 0; rr < 4; ++rr) acc[s][rr] = bv;
                }
                // x-part: sections 0..2, K=29, Wih persistent
                frag<384, 0, 3, 0, 29>(sRB + E_WI, sX, acc, col0, prow);
                // h-part: sections 3..5, K=128 streamed in 8 chunks
                for (int kc = 0; kc < NCH; ++kc) {
                    float* buf = bufs[kc & 1];
                    sts_enc(st, buf);
                    __syncthreads();
                    ldg_enc(st, eWhh, ((kc + 1) & (NCH - 1)) * KC);  // next (wraps: same W every pass/step)
                    frag<384, 3, 6, 3, KC>(buf, hc + kc * KC * 64, acc, col0, prow);
                    __syncthreads();
                }
                gru_epi(acc, hc, hn, j, prow);
            }
            __syncthreads();
            cur ^= 1;
        }
    }

    // ===================== decoder =====================
    {
        float* bufs[2] = { sRB + D_C0, sRB + D_C1 };
        float4 st[6];
        ldg_dec(st, dWih, dWhh, 0);
        __syncthreads();   // enc-region readers done before dec STS overwrites RB

        for (int t = 0; t < TSTEPS; ++t) {
            float* hc = sm + (cur ? OFF_H1 : OFF_H0);
            float* hn = sm + (cur ? OFF_H0 : OFF_H1);

            for (int pass = 0; pass < 2; ++pass) {
                const int prow = pass * 32 + rg * 4;
                ull acc[6][4];
#pragma unroll
                for (int s = 0; s < 6; ++s) {
                    ull bv = *(const ull*)(sB + 768 + s * 128 + col0);
#pragma unroll
                    for (int rr = 0; rr < 4; ++rr) acc[s][rr] = bv;
                }
                for (int kc = 0; kc < NCH; ++kc) {
                    float* buf = bufs[kc & 1];
                    sts_dec(st, buf);
                    __syncthreads();
                    ldg_dec(st, dWih, dWhh, ((kc + 1) & (NCH - 1)) * KC);
                    const float* op = hc + kc * KC * 64;
                    if (t == 0)  // xin = 0: gx = bih only, skip sections 0..2
                        frag<768, 3, 6, 0, KC>(buf, op, acc, col0, prow);
                    else         // xin == h: all 6 sections share operand h
                        frag<768, 0, 6, 0, KC>(buf, op, acc, col0, prow);
                    __syncthreads();
                }
                gru_epi(acc, hc, hn, j, prow);
            }
            __syncthreads();
            cur ^= 1;
        }
    }

    // ===================== heads =====================
    {
        float* hfin = sm + (cur ? OFF_H1 : OFF_H0);
        float* zb   = sm + (cur ? OFF_H0 : OFF_H1);   // reuse pong for z_cnn rows
        float* sDW  = sRB + H_DW;                     // [79][256]
        float* sHT  = sRB + H_HT;                     // h transposed [r][128]

        for (int i = tid; i < 64 * 128; i += THREADS) zb[i] = g_zc[(size_t)rb * 128 + i];
        for (int i = tid; i < 79 * 256; i += THREADS)
            sDW[i] = (i < 78 * 256) ? disw[i] : vw[i - 78 * 256];
        for (int i = tid; i < 64 * 128; i += THREADS) {
            int r = i >> 7, k = i & 127;
            sHT[i] = hfin[k * 64 + r];
        }
        __syncthreads();

        for (int o = tid; o < 64 * 79; o += THREADS) {
            int r = o / 79, c = o % 79;
            const ull* wp = (const ull*)(sDW + c * 256);
            const ull* zr = (const ull*)(zb + r * 128);
            const ull* hr = (const ull*)(sHT + r * 128);
            ull a2 = pk2(0.0f, 0.0f);
#pragma unroll 8
            for (int k = 0; k < 64; ++k) fma2(a2, zr[k], wp[k]);
#pragma unroll 8
            for (int k = 0; k < 64; ++k) fma2(a2, hr[k], wp[64 + k]);
            float lo, hi; upk2(a2, lo, hi);
            float acc = ((c < 78) ? disb[c] : vb[0]) + lo + hi;
            if (c < 78) out[(size_t)(rb + r) * 78 + c] = acc;
            else        out[(size_t)BATCH * 78 + rb + r] = acc;
        }
    }
}

// =============================================================================
// CNN: conv1 (27->16, 3x3, s2) + relu + conv2 (16->32, 2x2, s1) + relu
// =============================================================================
__global__ void __launch_bounds__(256, 1)
conv_k(const float* __restrict__ cnn,
       const float* __restrict__ w1, const float* __restrict__ b1,
       const float* __restrict__ w2, const float* __restrict__ b2)
{
    extern __shared__ float sms[];
    float* sin_ = sms;
    float* sw1  = sin_ + 16 * 1728;
    float* sw2  = sw1 + 3888;
    float* sx1  = sw2 + 2048;

    const int tid = threadIdx.x;
    const int b0  = blockIdx.x * 16;

    for (int i = tid; i < 16 * 1728; i += 256) sin_[i] = cnn[(size_t)b0 * 1728 + i];
    for (int i = tid; i < 3888; i += 256) sw1[i] = w1[i];
    for (int i = tid; i < 2048; i += 256) sw2[i] = w2[i];
    __syncthreads();

    const int bb = tid >> 4;
    const int c  = tid & 15;

    float acc[9];
    float bc = b1[c];
#pragma unroll
    for (int p = 0; p < 9; ++p) acc[p] = bc;
    for (int ky = 0; ky < 3; ++ky)
        for (int kx = 0; kx < 3; ++kx)
            for (int ic = 0; ic < 27; ++ic) {
                float w = sw1[c * 243 + ic * 9 + ky * 3 + kx];
#pragma unroll
                for (int i = 0; i < 3; ++i)
#pragma unroll
                    for (int jx = 0; jx < 3; ++jx)
                        acc[i * 3 + jx] = fmaf(sin_[((bb * 8 + 2 * i + ky) * 8 + 2 * jx + kx) * 27 + ic],
                                               w, acc[i * 3 + jx]);
            }
#pragma unroll
    for (int p = 0; p < 9; ++p) sx1[(bb * 16 + c) * 9 + p] = fmaxf(acc[p], 0.0f);
    __syncthreads();

    float a2[2][4];
#pragma unroll
    for (int q = 0; q < 2; ++q) {
        float bcc = b2[c + 16 * q];
#pragma unroll
        for (int p = 0; p < 4; ++p) a2[q][p] = bcc;
    }
    for (int ci = 0; ci < 16; ++ci) {
        float xv[9];
#pragma unroll
        for (int p = 0; p < 9; ++p) xv[p] = sx1[(bb * 16 + ci) * 9 + p];
#pragma unroll
        for (int q = 0; q < 2; ++q) {
            int c2 = c + 16 * q;
#pragma unroll
            for (int ky = 0; ky < 2; ++ky)
#pragma unroll
                for (int kx = 0; kx < 2; ++kx) {
                    float w = sw2[(c2 * 16 + ci) * 4 + ky * 2 + kx];
#pragma unroll
                    for (int i = 0; i < 2; ++i)
#pragma unroll
                        for (int jx = 0; jx < 2; ++jx)
                            a2[q][i * 2 + jx] = fmaf(xv[(i + ky) * 3 + (jx + kx)], w, a2[q][i * 2 + jx]);
                }
        }
    }
    float* outp = g_x2 + (size_t)(b0 + bb) * 128;
#pragma unroll
    for (int q = 0; q < 2; ++q)
#pragma unroll
        for (int p = 0; p < 4; ++p)
            outp[(c + 16 * q) * 4 + p] = fmaxf(a2[q][p], 0.0f);
}

// fc: z_cnn = relu(g_x2 @ fc_w^T + fc_b)
__global__ void fc_k(const float* __restrict__ W, const float* __restrict__ bias)
{
    int gid = blockIdx.x * 256 + threadIdx.x;
    int b = gid >> 7, jj = gid & 127;
    const float* xr = g_x2 + (size_t)b * 128;
    const float* wr = W + (size_t)jj * 128;
    float acc = bias[jj];
#pragma unroll 8
    for (int k = 0; k < 128; ++k) acc = fmaf(xr[k], wr[k], acc);
    g_zc[gid] = fmaxf(acc, 0.0f);
}

// =============================================================================
extern "C" void kernel_launch(void* const* d_in, const int* in_sizes, int n_in,
                              void* d_out, int out_size)
{
    const float* cnn  = (const float*)d_in[0];
    const float* lin  = (const float*)d_in[1];
    const float* c1w  = (const float*)d_in[2];
    const float* c1b  = (const float*)d_in[3];
    const float* c2w  = (const float*)d_in[4];
    const float* c2b  = (const float*)d_in[5];
    const float* fcw  = (const float*)d_in[6];
    const float* fcb  = (const float*)d_in[7];
    const float* eWih = (const float*)d_in[8];
    const float* eWhh = (const float*)d_in[9];
    const float* ebih = (const float*)d_in[10];
    const float* ebhh = (const float*)d_in[11];
    const float* dWih = (const float*)d_in[12];
    const float* dWhh = (const float*)d_in[13];
    const float* dbih = (const float*)d_in[14];
    const float* dbhh = (const float*)d_in[15];
    const float* disw = (const float*)d_in[16];
    const float* disb = (const float*)d_in[17];
    const float* vw   = (const float*)d_in[18];
    const float* vb   = (const float*)d_in[19];
    float* out = (float*)d_out;

    cudaFuncSetAttribute(conv_k,  cudaFuncAttributeMaxDynamicSharedMemorySize, CONV_SMEM);
    cudaFuncSetAttribute(recur_k, cudaFuncAttributeMaxDynamicSharedMemorySize, SMEM_BYTES);

    conv_k<<<BATCH / 16, 256, CONV_SMEM>>>(cnn, c1w, c1b, c2w, c2b);
    fc_k<<<BATCH * 128 / 256, 256>>>(fcw, fcb);

    recur_k<<<NCTA, THREADS, SMEM_BYTES>>>(lin,
                                           eWih, eWhh, ebih, ebhh,
                                           dWih, dWhh, dbih, dbhh,
                                           disw, disb, vw, vb, out);
}

// round 6
// speedup vs baseline: 1.4857x; 1.4840x over previous
#include <cuda_runtime.h>
#include <cstdint>

typedef unsigned long long ull;

#define BATCH 8192
#define TSTEPS 64
#define NCTA 128
#define THREADS 512

__device__ float g_x2[BATCH * 128];
__device__ float g_zc[BATCH * 128];
__device__ float g_eWT[128 * 384];   // enc Whh^T [k][j]
__device__ float g_dWT[128 * 768];   // dec [Wih|Whh]^T [k][j]

// smem layout (float offsets)
constexpr int O_H0   = 0;        // h ping [k=128][row=64]
constexpr int O_H1   = 8192;     // h pong
constexpr int O_BUF0 = 16384;    // chunk buf 0 (12288 floats = 48KB)
constexpr int O_BUF1 = 28672;    // chunk buf 1
constexpr int O_WI   = 40960;    // enc Wih^T [29][384] = 11136
constexpr int O_X    = 52096;    // x_t^T [29][64] = 1856
constexpr int O_B    = 53952;    // biases 1536
constexpr int MBAR_BYTE  = 55488 * 4;
constexpr int SMEM_BYTES = MBAR_BYTE + 16;   // 221968
constexpr int NSEQ = 512 + 1024;             // enc 64*2*4, dec 64*2*8
constexpr int CH_BYTES = 49152;
constexpr int CONV_SMEM = (16*1728 + 3888 + 2048 + 16*144) * 4;

__device__ __forceinline__ ull pk2(float a, float b) {
    ull r; asm("mov.b64 %0, {%1,%2};" : "=l"(r) : "f"(a), "f"(b)); return r;
}
__device__ __forceinline__ void upk2(ull v, float& a, float& b) {
    asm("mov.b64 {%0,%1}, %2;" : "=f"(a), "=f"(b) : "l"(v));
}
__device__ __forceinline__ void fma2(ull& d, ull a, ull b) {
    asm("fma.rn.f32x2 %0, %1, %2, %0;" : "+l"(d) : "l"(a), "l"(b));
}
__device__ __forceinline__ float sigf(float x)     { return 1.0f / (1.0f + __expf(-x)); }
__device__ __forceinline__ float tanhfast(float x) { return 2.0f / (1.0f + __expf(-2.0f * x)) - 1.0f; }
__device__ __forceinline__ uint32_t smem_u32(const void* p) {
    uint32_t a;
    asm("{ .reg .u64 t; cvta.to.shared.u64 t, %1; cvt.u32.u64 %0, t; }" : "=r"(a) : "l"(p));
    return a;
}
__device__ __forceinline__ void mbar_init(uint32_t bar, uint32_t cnt) {
    asm volatile("mbarrier.init.shared.b64 [%0], %1;" :: "r"(bar), "r"(cnt) : "memory");
}
__device__ __forceinline__ void wait_full(uint32_t bar, uint32_t parity) {
    asm volatile(
        "{\n\t.reg .pred P;\n\t"
        "WL_%=:\n\t"
        "mbarrier.try_wait.parity.acquire.cta.shared::cta.b64 P, [%0], %1, 0x989680;\n\t"
        "@P bra.uni WD_%=;\n\t"
        "bra.uni WL_%=;\n\t"
        "WD_%=:\n\t}"
        :: "r"(bar), "r"(parity) : "memory");
}
// producer: one 48KB bulk copy of chunk s into buf (s&1)
__device__ __forceinline__ void issue_chunk(int s, uint32_t smb) {
    uint32_t dst = smb + (uint32_t)(O_BUF0 + (s & 1) * 12288) * 4;
    uint32_t bar = smb + MBAR_BYTE + (s & 1) * 8;
    const float* src = (s < 512) ? (g_eWT + (size_t)(s & 3) * 32 * 384)
                                 : (g_dWT + (size_t)(s & 7) * 16 * 768);
    asm volatile("mbarrier.arrive.expect_tx.shared.b64 _, [%0], %1;"
                 :: "r"(bar), "r"((uint32_t)CH_BYTES) : "memory");
    asm volatile("cp.async.bulk.shared::cluster.global.mbarrier::complete_tx::bytes "
                 "[%0], [%1], %2, [%3];"
                 :: "r"(dst), "l"(src), "r"((uint32_t)CH_BYTES), "r"(bar) : "memory");
}

// NS sections into acc[AO..], KN k-iters, weight row width WW.
template <int NS, int KN, int WW, int AO>
__device__ __forceinline__ void fragT(const float* __restrict__ w,
                                      const float* __restrict__ op,
                                      ull (&acc)[6][4], int col2, int prow)
{
#pragma unroll 4
    for (int k = 0; k < KN; ++k) {
        float4 hv = *(const float4*)(op + k * 64 + prow);
        ull h0 = pk2(hv.x, hv.x), h1 = pk2(hv.y, hv.y);
        ull h2 = pk2(hv.z, hv.z), h3 = pk2(hv.w, hv.w);
#pragma unroll
        for (int s = 0; s < NS; ++s) {
            ull wv = *(const ull*)(w + k * WW + s * 128 + col2);
            fma2(acc[AO+s][0], h0, wv); fma2(acc[AO+s][1], h1, wv);
            fma2(acc[AO+s][2], h2, wv); fma2(acc[AO+s][3], h3, wv);
        }
    }
}

__device__ __forceinline__ void gru_epi(ull (&acc)[6][4], const float* __restrict__ hc,
                                        float* __restrict__ hn, int j, int prow)
{
#pragma unroll
    for (int rr = 0; rr < 4; ++rr) {
        int r = prow + rr;
        float xr0, xr1, xz0, xz1, xn0, xn1, hr0, hr1, hz0, hz1, hn0, hn1;
        upk2(acc[0][rr], xr0, xr1); upk2(acc[1][rr], xz0, xz1); upk2(acc[2][rr], xn0, xn1);
        upk2(acc[3][rr], hr0, hr1); upk2(acc[4][rr], hz0, hz1); upk2(acc[5][rr], hn0, hn1);
        float rg0 = sigf(xr0 + hr0), rg1 = sigf(xr1 + hr1);
        float z0  = sigf(xz0 + hz0), z1  = sigf(xz1 + hz1);
        float n0  = tanhfast(xn0 + rg0 * hn0), n1 = tanhfast(xn1 + rg1 * hn1);
        float hp0 = hc[j * 64 + r], hp1 = hc[(j + 1) * 64 + r];
        hn[j * 64 + r]       = (1.0f - z0) * n0 + z0 * hp0;
        hn[(j + 1) * 64 + r] = (1.0f - z1) * n1 + z1 * hp1;
    }
}

// one-shot weight transpose
__global__ void wt_k(const float* __restrict__ eWhh,
                     const float* __restrict__ dWih, const float* __restrict__ dWhh)
{
    int i = blockIdx.x * 256 + threadIdx.x;
    if (i < 128 * 384) {
        int k = i / 384, j = i % 384;
        g_eWT[i] = eWhh[(size_t)j * 128 + k];
    } else if (i < 128 * 384 + 128 * 768) {
        int e = i - 128 * 384;
        int k = e / 768, j = e % 768;
        g_dWT[e] = (j < 384) ? dWih[(size_t)j * 128 + k]
                             : dWhh[(size_t)(j - 384) * 128 + k];
    }
}

// ============ persistent recurrence: 128 CTAs x 64 batch rows ============
__global__ void __launch_bounds__(THREADS, 1)
recur_k(const float* __restrict__ lin, const float* __restrict__ eWih,
        const float* __restrict__ ebih, const float* __restrict__ ebhh,
        const float* __restrict__ dbih, const float* __restrict__ dbhh,
        const float* __restrict__ disw, const float* __restrict__ disb,
        const float* __restrict__ vw,   const float* __restrict__ vb,
        float* __restrict__ out)
{
    extern __shared__ float sm[];
    const uint32_t smb = smem_u32(sm);
    const int tid  = threadIdx.x;
    const int rb   = blockIdx.x * 64;
    const int rg   = tid & 7;          // row group of 4
    const int col2 = 2 * (tid >> 3);   // feature pair

    for (int i = tid; i < 8192; i += THREADS) sm[O_H0 + i] = 0.0f;
    for (int i = tid; i < 384; i += THREADS) {
        sm[O_B + i]       = ebih[i];  sm[O_B + 384 + i]  = ebhh[i];
        sm[O_B + 768 + i] = dbih[i];  sm[O_B + 1152 + i] = dbhh[i];
    }
    for (int i = tid; i < 29 * 384; i += THREADS) {
        int k = i / 384, j = i % 384;
        sm[O_WI + k * 384 + j] = eWih[(size_t)j * 29 + k];
    }
    if (tid == 0) { mbar_init(smb + MBAR_BYTE, 1); mbar_init(smb + MBAR_BYTE + 8, 1); }
    __syncthreads();
    if (tid == 0) {
        asm volatile("fence.proxy.async.shared::cta;" ::: "memory");
        issue_chunk(0, smb); issue_chunk(1, smb);
    }

    float* hc = sm + O_H0;
    float* hn = sm + O_H1;
    int seq = 0;

    // -------- encoder --------
    for (int t = 0; t < TSTEPS; ++t) {
        for (int i = tid; i < 64 * 29; i += THREADS) {
            int r = i / 29, k = i % 29;
            sm[O_X + k * 64 + r] = lin[(size_t)(rb + r) * 1856 + (size_t)t * 29 + k];
        }
        __syncthreads();
#pragma unroll 1
        for (int pass = 0; pass < 2; ++pass) {
            const int prow = pass * 32 + rg * 4;
            ull acc[6][4];
#pragma unroll
            for (int s = 0; s < 3; ++s) {
                ull bi = *(const ull*)(sm + O_B + s * 128 + col2);
                ull bh = *(const ull*)(sm + O_B + 384 + s * 128 + col2);
#pragma unroll
                for (int rr = 0; rr < 4; ++rr) { acc[s][rr] = bi; acc[3+s][rr] = bh; }
            }
            fragT<3, 29, 384, 0>(sm + O_WI, sm + O_X, acc, col2, prow);
#pragma unroll 1
            for (int kc = 0; kc < 4; ++kc) {
                const float* buf = sm + O_BUF0 + (seq & 1) * 12288;
                wait_full(smb + MBAR_BYTE + (seq & 1) * 8, (seq >> 1) & 1);
                fragT<3, 32, 384, 3>(buf, hc + kc * 32 * 64, acc, col2, prow);
                __syncthreads();
                if (tid == 0 && seq + 2 < NSEQ) issue_chunk(seq + 2, smb);
                ++seq;
            }
            gru_epi(acc, hc, hn, col2, prow);
        }
        float* tp = hc; hc = hn; hn = tp;
        // next iteration's x-stage __syncthreads orders epi writes vs reads
    }

    // -------- decoder --------
    for (int t = 0; t < TSTEPS; ++t) {
        __syncthreads();
#pragma unroll 1
        for (int pass = 0; pass < 2; ++pass) {
            const int prow = pass * 32 + rg * 4;
            ull acc[6][4];
#pragma unroll
            for (int s = 0; s < 3; ++s) {
                ull bi = *(const ull*)(sm + O_B + 768 + s * 128 + col2);
                ull bh = *(const ull*)(sm + O_B + 1152 + s * 128 + col2);
#pragma unroll
                for (int rr = 0; rr < 4; ++rr) { acc[s][rr] = bi; acc[3+s][rr] = bh; }
            }
#pragma unroll 1
            for (int kc = 0; kc < 8; ++kc) {
                const float* buf = sm + O_BUF0 + (seq & 1) * 12288;
                wait_full(smb + MBAR_BYTE + (seq & 1) * 8, (seq >> 1) & 1);
                if (t == 0)
                    fragT<3, 16, 768, 3>(buf + 384, hc + kc * 16 * 64, acc, col2, prow);
                else
                    fragT<6, 16, 768, 0>(buf, hc + kc * 16 * 64, acc, col2, prow);
                __syncthreads();
                if (tid == 0 && seq + 2 < NSEQ) issue_chunk(seq + 2, smb);
                ++seq;
            }
            gru_epi(acc, hc, hn, col2, prow);
        }
        float* tp = hc; hc = hn; hn = tp;
    }

    // -------- heads --------
    __syncthreads();
    {
        float* hfin = hc;
        float* zb   = hn;
        float* sDW  = sm + O_BUF0;     // [79][256] = 20224 fl
        float* sHT  = sm + O_WI;       // [64][128]

        for (int i = tid; i < 64 * 128; i += THREADS) zb[i] = g_zc[(size_t)rb * 128 + i];
        for (int i = tid; i < 79 * 256; i += THREADS)
            sDW[i] = (i < 78 * 256) ? disw[i] : vw[i - 78 * 256];
        for (int i = tid; i < 64 * 128; i += THREADS) {
            int r = i >> 7, k = i & 127;
            sHT[i] = hfin[k * 64 + r];
        }
        __syncthreads();

        for (int o = tid; o < 64 * 79; o += THREADS) {
            int r = o / 79, c = o % 79;
            const ull* wp = (const ull*)(sDW + c * 256);
            const ull* zr = (const ull*)(zb + r * 128);
            const ull* hr = (const ull*)(sHT + r * 128);
            ull a2 = pk2(0.0f, 0.0f);
#pragma unroll 8
            for (int k = 0; k < 64; ++k) fma2(a2, zr[k], wp[k]);
#pragma unroll 8
            for (int k = 0; k < 64; ++k) fma2(a2, hr[k], wp[64 + k]);
            float lo, hi; upk2(a2, lo, hi);
            float acc = ((c < 78) ? disb[c] : vb[0]) + lo + hi;
            if (c < 78) out[(size_t)(rb + r) * 78 + c] = acc;
            else        out[(size_t)BATCH * 78 + rb + r] = acc;
        }
    }
}

// ============ CNN (unchanged from R3) ============
__global__ void __launch_bounds__(256, 1)
conv_k(const float* __restrict__ cnn,
       const float* __restrict__ w1, const float* __restrict__ b1,
       const float* __restrict__ w2, const float* __restrict__ b2)
{
    extern __shared__ float sms[];
    float* sin_ = sms;
    float* sw1  = sin_ + 16 * 1728;
    float* sw2  = sw1 + 3888;
    float* sx1  = sw2 + 2048;
    const int tid = threadIdx.x;
    const int b0  = blockIdx.x * 16;

    for (int i = tid; i < 16 * 1728; i += 256) sin_[i] = cnn[(size_t)b0 * 1728 + i];
    for (int i = tid; i < 3888; i += 256) sw1[i] = w1[i];
    for (int i = tid; i < 2048; i += 256) sw2[i] = w2[i];
    __syncthreads();

    const int bb = tid >> 4, c = tid & 15;
    float acc[9];
    float bc = b1[c];
#pragma unroll
    for (int p = 0; p < 9; ++p) acc[p] = bc;
    for (int ky = 0; ky < 3; ++ky)
        for (int kx = 0; kx < 3; ++kx)
            for (int ic = 0; ic < 27; ++ic) {
                float w = sw1[c * 243 + ic * 9 + ky * 3 + kx];
#pragma unroll
                for (int i = 0; i < 3; ++i)
#pragma unroll
                    for (int jx = 0; jx < 3; ++jx)
                        acc[i*3+jx] = fmaf(sin_[((bb*8 + 2*i + ky)*8 + 2*jx + kx)*27 + ic], w, acc[i*3+jx]);
            }
#pragma unroll
    for (int p = 0; p < 9; ++p) sx1[(bb * 16 + c) * 9 + p] = fmaxf(acc[p], 0.0f);
    __syncthreads();

    float a2[2][4];
#pragma unroll
    for (int q = 0; q < 2; ++q) {
        float bcc = b2[c + 16 * q];
#pragma unroll
        for (int p = 0; p < 4; ++p) a2[q][p] = bcc;
    }
    for (int ci = 0; ci < 16; ++ci) {
        float xv[9];
#pragma unroll
        for (int p = 0; p < 9; ++p) xv[p] = sx1[(bb * 16 + ci) * 9 + p];
#pragma unroll
        for (int q = 0; q < 2; ++q) {
            int c2 = c + 16 * q;
#pragma unroll
            for (int ky = 0; ky < 2; ++ky)
#pragma unroll
                for (int kx = 0; kx < 2; ++kx) {
                    float w = sw2[(c2 * 16 + ci) * 4 + ky * 2 + kx];
#pragma unroll
                    for (int i = 0; i < 2; ++i)
#pragma unroll
                        for (int jx = 0; jx < 2; ++jx)
                            a2[q][i*2+jx] = fmaf(xv[(i+ky)*3 + (jx+kx)], w, a2[q][i*2+jx]);
                }
        }
    }
    float* outp = g_x2 + (size_t)(b0 + bb) * 128;
#pragma unroll
    for (int q = 0; q < 2; ++q)
#pragma unroll
        for (int p = 0; p < 4; ++p)
            outp[(c + 16 * q) * 4 + p] = fmaxf(a2[q][p], 0.0f);
}

__global__ void fc_k(const float* __restrict__ W, const float* __restrict__ bias)
{
    int gid = blockIdx.x * 256 + threadIdx.x;
    int b = gid >> 7, jj = gid & 127;
    const float* xr = g_x2 + (size_t)b * 128;
    const float* wr = W + (size_t)jj * 128;
    float acc = bias[jj];
#pragma unroll 8
    for (int k = 0; k < 128; ++k) acc = fmaf(xr[k], wr[k], acc);
    g_zc[gid] = fmaxf(acc, 0.0f);
}

extern "C" void kernel_launch(void* const* d_in, const int* in_sizes, int n_in,
                              void* d_out, int out_size)
{
    const float* cnn  = (const float*)d_in[0];
    const float* lin  = (const float*)d_in[1];
    const float* c1w  = (const float*)d_in[2];
    const float* c1b  = (const float*)d_in[3];
    const float* c2w  = (const float*)d_in[4];
    const float* c2b  = (const float*)d_in[5];
    const float* fcw  = (const float*)d_in[6];
    const float* fcb  = (const float*)d_in[7];
    const float* eWih = (const float*)d_in[8];
    const float* eWhh = (const float*)d_in[9];
    const float* ebih = (const float*)d_in[10];
    const float* ebhh = (const float*)d_in[11];
    const float* dWih = (const float*)d_in[12];
    const float* dWhh = (const float*)d_in[13];
    const float* dbih = (const float*)d_in[14];
    const float* dbhh = (const float*)d_in[15];
    const float* disw = (const float*)d_in[16];
    const float* disb = (const float*)d_in[17];
    const float* vw   = (const float*)d_in[18];
    const float* vb   = (const float*)d_in[19];
    float* out = (float*)d_out;

    cudaFuncSetAttribute(conv_k,  cudaFuncAttributeMaxDynamicSharedMemorySize, CONV_SMEM);
    cudaFuncSetAttribute(recur_k, cudaFuncAttributeMaxDynamicSharedMemorySize, SMEM_BYTES);

    wt_k<<<(128*384 + 128*768 + 255) / 256, 256>>>(eWhh, dWih, dWhh);
    conv_k<<<BATCH / 16, 256, CONV_SMEM>>>(cnn, c1w, c1b, c2w, c2b);
    fc_k<<<BATCH * 128 / 256, 256>>>(fcw, fcb);

    recur_k<<<NCTA, THREADS, SMEM_BYTES>>>(lin, eWih,
                                           ebih, ebhh, dbih, dbhh,
                                           disw, disb, vw, vb, out);
}

// round 7
// speedup vs baseline: 1.5596x; 1.0497x over previous
#include <cuda_runtime.h>
#include <cstdint>

typedef unsigned long long ull;

#define BATCH 8192
#define TSTEPS 64
#define NCTA 128
#define THREADS 512

__device__ float g_x2[BATCH * 128];
__device__ float g_zc[BATCH * 128];
__device__ float g_eWT[128 * 384];   // enc Whh^T [k][j]
__device__ float g_dWT[128 * 768];   // dec [Wih|Whh]^T [k][j]

// smem layout (float offsets)
constexpr int O_H0   = 0;        // h ping [k=128][row=64]
constexpr int O_H1   = 8192;     // h pong
constexpr int O_BUF0 = 16384;    // chunk buf 0 (12288 floats = 48KB)
constexpr int O_BUF1 = 28672;    // chunk buf 1
constexpr int O_WI   = 40960;    // enc Wih^T [29][384] = 11136
constexpr int O_X    = 52096;    // x_t^T [29][64] = 1856
constexpr int O_B    = 53952;    // biases 1536
constexpr int MBAR_BYTE  = 55488 * 4;        // full0,full1,empty0,empty1
constexpr int SMEM_BYTES = MBAR_BYTE + 32;
constexpr int NSEQ = 512 + 1024;             // enc 64*2*4, dec 64*2*8
constexpr int CH_BYTES = 49152;
constexpr int CONV_SMEM = (8*1728 + 3888 + 2048 + 8*144) * 4;   // 83648

__device__ __forceinline__ ull pk2(float a, float b) {
    ull r; asm("mov.b64 %0, {%1,%2};" : "=l"(r) : "f"(a), "f"(b)); return r;
}
__device__ __forceinline__ void upk2(ull v, float& a, float& b) {
    asm("mov.b64 {%0,%1}, %2;" : "=f"(a), "=f"(b) : "l"(v));
}
__device__ __forceinline__ void fma2(ull& d, ull a, ull b) {
    asm("fma.rn.f32x2 %0, %1, %2, %0;" : "+l"(d) : "l"(a), "l"(b));
}
__device__ __forceinline__ float sigf(float x)     { return 1.0f / (1.0f + __expf(-x)); }
__device__ __forceinline__ float tanhfast(float x) { return 2.0f / (1.0f + __expf(-2.0f * x)) - 1.0f; }
__device__ __forceinline__ uint32_t smem_u32(const void* p) {
    uint32_t a;
    asm("{ .reg .u64 t; cvta.to.shared.u64 t, %1; cvt.u32.u64 %0, t; }" : "=r"(a) : "l"(p));
    return a;
}
__device__ __forceinline__ void mbar_init(uint32_t bar, uint32_t cnt) {
    asm volatile("mbarrier.init.shared.b64 [%0], %1;" :: "r"(bar), "r"(cnt) : "memory");
}
__device__ __forceinline__ void mbar_arrive(uint32_t bar) {
    asm volatile("mbarrier.arrive.release.cta.shared::cta.b64 _, [%0];" :: "r"(bar) : "memory");
}
__device__ __forceinline__ void wait_par(uint32_t bar, uint32_t parity) {
    asm volatile(
        "{\n\t.reg .pred P;\n\t"
        "WL_%=:\n\t"
        "mbarrier.try_wait.parity.acquire.cta.shared::cta.b64 P, [%0], %1, 0x989680;\n\t"
        "@P bra.uni WD_%=;\n\t"
        "bra.uni WL_%=;\n\t"
        "WD_%=:\n\t}"
        :: "r"(bar), "r"(parity) : "memory");
}
// producer: one 48KB bulk copy of chunk s into buf (s&1)
__device__ __forceinline__ void issue_chunk(int s, uint32_t smb) {
    uint32_t dst = smb + (uint32_t)(O_BUF0 + (s & 1) * 12288) * 4;
    uint32_t bar = smb + MBAR_BYTE + (s & 1) * 8;
    const float* src = (s < 512) ? (g_eWT + (size_t)(s & 3) * 32 * 384)
                                 : (g_dWT + (size_t)(s & 7) * 16 * 768);
    asm volatile("mbarrier.arrive.expect_tx.shared.b64 _, [%0], %1;"
                 :: "r"(bar), "r"((uint32_t)CH_BYTES) : "memory");
    asm volatile("cp.async.bulk.shared::cluster.global.mbarrier::complete_tx::bytes "
                 "[%0], [%1], %2, [%3];"
                 :: "r"(dst), "l"(src), "r"((uint32_t)CH_BYTES), "r"(bar) : "memory");
}
// consumer-side chunk release + producer refill. Call after last read of chunk s.
__device__ __forceinline__ void release_chunk(int s, uint32_t smb, int tid) {
    uint32_t ebar = smb + MBAR_BYTE + 16 + (s & 1) * 8;
    if ((tid & 31) == 0) mbar_arrive(ebar);
    if (tid == 0 && s + 2 < NSEQ) {
        wait_par(ebar, (uint32_t)((s >> 1) & 1));   // all 16 warps released buf
        issue_chunk(s + 2, smb);
    }
}

// NS sections into acc[AO..], KN k-iters, weight row width WW.
template <int NS, int KN, int WW, int AO>
__device__ __forceinline__ void fragT(const float* __restrict__ w,
                                      const float* __restrict__ op,
                                      ull (&acc)[6][4], int col2, int prow)
{
#pragma unroll 8
    for (int k = 0; k < KN; ++k) {
        float4 hv = *(const float4*)(op + k * 64 + prow);
        ull h0 = pk2(hv.x, hv.x), h1 = pk2(hv.y, hv.y);
        ull h2 = pk2(hv.z, hv.z), h3 = pk2(hv.w, hv.w);
#pragma unroll
        for (int s = 0; s < NS; ++s) {
            ull wv = *(const ull*)(w + k * WW + s * 128 + col2);
            fma2(acc[AO+s][0], h0, wv); fma2(acc[AO+s][1], h1, wv);
            fma2(acc[AO+s][2], h2, wv); fma2(acc[AO+s][3], h3, wv);
        }
    }
}

__device__ __forceinline__ void gru_epi(ull (&acc)[6][4], const float* __restrict__ hc,
                                        float* __restrict__ hn, int j, int prow)
{
#pragma unroll
    for (int rr = 0; rr < 4; ++rr) {
        int r = prow + rr;
        float xr0, xr1, xz0, xz1, xn0, xn1, hr0, hr1, hz0, hz1, hn0, hn1;
        upk2(acc[0][rr], xr0, xr1); upk2(acc[1][rr], xz0, xz1); upk2(acc[2][rr], xn0, xn1);
        upk2(acc[3][rr], hr0, hr1); upk2(acc[4][rr], hz0, hz1); upk2(acc[5][rr], hn0, hn1);
        float rg0 = sigf(xr0 + hr0), rg1 = sigf(xr1 + hr1);
        float z0  = sigf(xz0 + hz0), z1  = sigf(xz1 + hz1);
        float n0  = tanhfast(xn0 + rg0 * hn0), n1 = tanhfast(xn1 + rg1 * hn1);
        float hp0 = hc[j * 64 + r], hp1 = hc[(j + 1) * 64 + r];
        hn[j * 64 + r]       = (1.0f - z0) * n0 + z0 * hp0;
        hn[(j + 1) * 64 + r] = (1.0f - z1) * n1 + z1 * hp1;
    }
}

// one-shot weight transpose
__global__ void wt_k(const float* __restrict__ eWhh,
                     const float* __restrict__ dWih, const float* __restrict__ dWhh)
{
    int i = blockIdx.x * 256 + threadIdx.x;
    if (i < 128 * 384) {
        int k = i / 384, j = i % 384;
        g_eWT[i] = eWhh[(size_t)j * 128 + k];
    } else if (i < 128 * 384 + 128 * 768) {
        int e = i - 128 * 384;
        int k = e / 768, j = e % 768;
        g_dWT[e] = (j < 384) ? dWih[(size_t)j * 128 + k]
                             : dWhh[(size_t)(j - 384) * 128 + k];
    }
}

// ============ persistent recurrence: 128 CTAs x 64 batch rows ============
__global__ void __launch_bounds__(THREADS, 1)
recur_k(const float* __restrict__ lin, const float* __restrict__ eWih,
        const float* __restrict__ ebih, const float* __restrict__ ebhh,
        const float* __restrict__ dbih, const float* __restrict__ dbhh,
        const float* __restrict__ disw, const float* __restrict__ disb,
        const float* __restrict__ vw,   const float* __restrict__ vb,
        float* __restrict__ out)
{
    extern __shared__ float sm[];
    const uint32_t smb = smem_u32(sm);
    const int tid  = threadIdx.x;
    const int rb   = blockIdx.x * 64;
    const int rg   = tid & 7;          // row group of 4
    const int col2 = 2 * (tid >> 3);   // feature pair

    for (int i = tid; i < 8192; i += THREADS) sm[O_H0 + i] = 0.0f;
    for (int i = tid; i < 384; i += THREADS) {
        sm[O_B + i]       = ebih[i];  sm[O_B + 384 + i]  = ebhh[i];
        sm[O_B + 768 + i] = dbih[i];  sm[O_B + 1152 + i] = dbhh[i];
    }
    for (int i = tid; i < 29 * 384; i += THREADS) {
        int k = i / 384, j = i % 384;
        sm[O_WI + k * 384 + j] = eWih[(size_t)j * 29 + k];
    }
    if (tid == 0) {
        mbar_init(smb + MBAR_BYTE,      1);   // full0
        mbar_init(smb + MBAR_BYTE + 8,  1);   // full1
        mbar_init(smb + MBAR_BYTE + 16, 16);  // empty0 (16 warps)
        mbar_init(smb + MBAR_BYTE + 24, 16);  // empty1
    }
    __syncthreads();
    if (tid == 0) {
        asm volatile("fence.proxy.async.shared::cta;" ::: "memory");
        issue_chunk(0, smb); issue_chunk(1, smb);
    }

    float* hc = sm + O_H0;
    float* hn = sm + O_H1;
    int seq = 0;

    // -------- encoder --------
    for (int t = 0; t < TSTEPS; ++t) {
        __syncthreads();   // prev step epi writes / x readers done
        for (int i = tid; i < 64 * 29; i += THREADS) {
            int r = i / 29, k = i % 29;
            sm[O_X + k * 64 + r] = lin[(size_t)(rb + r) * 1856 + (size_t)t * 29 + k];
        }
        __syncthreads();
#pragma unroll 1
        for (int pass = 0; pass < 2; ++pass) {
            const int prow = pass * 32 + rg * 4;
            ull acc[6][4];
#pragma unroll
            for (int s = 0; s < 3; ++s) {
                ull bi = *(const ull*)(sm + O_B + s * 128 + col2);
                ull bh = *(const ull*)(sm + O_B + 384 + s * 128 + col2);
#pragma unroll
                for (int rr = 0; rr < 4; ++rr) { acc[s][rr] = bi; acc[3+s][rr] = bh; }
            }
            fragT<3, 29, 384, 0>(sm + O_WI, sm + O_X, acc, col2, prow);
#pragma unroll 1
            for (int kc = 0; kc < 4; ++kc) {
                const float* buf = sm + O_BUF0 + (seq & 1) * 12288;
                wait_par(smb + MBAR_BYTE + (seq & 1) * 8, (seq >> 1) & 1);
                fragT<3, 32, 384, 3>(buf, hc + kc * 32 * 64, acc, col2, prow);
                release_chunk(seq, smb, tid);
                ++seq;
            }
            gru_epi(acc, hc, hn, col2, prow);
        }
        float* tp = hc; hc = hn; hn = tp;
    }

    // -------- decoder --------
    for (int t = 0; t < TSTEPS; ++t) {
        __syncthreads();   // prev step epi writes done
#pragma unroll 1
        for (int pass = 0; pass < 2; ++pass) {
            const int prow = pass * 32 + rg * 4;
            ull acc[6][4];
#pragma unroll
            for (int s = 0; s < 3; ++s) {
                ull bi = *(const ull*)(sm + O_B + 768 + s * 128 + col2);
                ull bh = *(const ull*)(sm + O_B + 1152 + s * 128 + col2);
#pragma unroll
                for (int rr = 0; rr < 4; ++rr) { acc[s][rr] = bi; acc[3+s][rr] = bh; }
            }
#pragma unroll 1
            for (int kc = 0; kc < 8; ++kc) {
                const float* buf = sm + O_BUF0 + (seq & 1) * 12288;
                wait_par(smb + MBAR_BYTE + (seq & 1) * 8, (seq >> 1) & 1);
                if (t == 0)
                    fragT<3, 16, 768, 3>(buf + 384, hc + kc * 16 * 64, acc, col2, prow);
                else
                    fragT<6, 16, 768, 0>(buf, hc + kc * 16 * 64, acc, col2, prow);
                release_chunk(seq, smb, tid);
                ++seq;
            }
            gru_epi(acc, hc, hn, col2, prow);
        }
        float* tp = hc; hc = hn; hn = tp;
    }

    // -------- heads --------
    __syncthreads();
    {
        float* hfin = hc;
        float* zb   = hn;
        float* sDW  = sm + O_BUF0;     // [79][256] = 20224 fl
        float* sHT  = sm + O_WI;       // [64][128]

        for (int i = tid; i < 64 * 128; i += THREADS) zb[i] = g_zc[(size_t)rb * 128 + i];
        for (int i = tid; i < 79 * 256; i += THREADS)
            sDW[i] = (i < 78 * 256) ? disw[i] : vw[i - 78 * 256];
        for (int i = tid; i < 64 * 128; i += THREADS) {
            int r = i >> 7, k = i & 127;
            sHT[i] = hfin[k * 64 + r];
        }
        __syncthreads();

        for (int o = tid; o < 64 * 79; o += THREADS) {
            int r = o / 79, c = o % 79;
            const ull* wp = (const ull*)(sDW + c * 256);
            const ull* zr = (const ull*)(zb + r * 128);
            const ull* hr = (const ull*)(sHT + r * 128);
            ull a2 = pk2(0.0f, 0.0f);
#pragma unroll 8
            for (int k = 0; k < 64; ++k) fma2(a2, zr[k], wp[k]);
#pragma unroll 8
            for (int k = 0; k < 64; ++k) fma2(a2, hr[k], wp[64 + k]);
            float lo, hi; upk2(a2, lo, hi);
            float acc = ((c < 78) ? disb[c] : vb[0]) + lo + hi;
            if (c < 78) out[(size_t)(rb + r) * 78 + c] = acc;
            else        out[(size_t)BATCH * 78 + rb + r] = acc;
        }
    }
}

// ============ CNN: 8 imgs/block, 128 threads, 2 CTAs/SM ============
__global__ void __launch_bounds__(128, 2)
conv_k(const float* __restrict__ cnn,
       const float* __restrict__ w1, const float* __restrict__ b1,
       const float* __restrict__ w2, const float* __restrict__ b2)
{
    extern __shared__ float sms[];
    float* sin_ = sms;                // [8][8][8][27]
    float* sw1  = sin_ + 8 * 1728;    // 3888
    float* sw2  = sw1 + 3888;         // 2048
    float* sx1  = sw2 + 2048;         // [8][16][3][3]
    const int tid = threadIdx.x;
    const int b0  = blockIdx.x * 8;

    for (int i = tid; i < 8 * 1728; i += 128) sin_[i] = cnn[(size_t)b0 * 1728 + i];
    for (int i = tid; i < 3888; i += 128) sw1[i] = w1[i];
    for (int i = tid; i < 2048; i += 128) sw2[i] = w2[i];
    __syncthreads();

    const int bb = tid >> 4, c = tid & 15;   // bb 0..7, c 0..15
    float acc[9];
    float bc = b1[c];
#pragma unroll
    for (int p = 0; p < 9; ++p) acc[p] = bc;
    for (int ky = 0; ky < 3; ++ky)
        for (int kx = 0; kx < 3; ++kx)
            for (int ic = 0; ic < 27; ++ic) {
                float w = sw1[c * 243 + ic * 9 + ky * 3 + kx];
#pragma unroll
                for (int i = 0; i < 3; ++i)
#pragma unroll
                    for (int jx = 0; jx < 3; ++jx)
                        acc[i*3+jx] = fmaf(sin_[((bb*8 + 2*i + ky)*8 + 2*jx + kx)*27 + ic], w, acc[i*3+jx]);
            }
#pragma unroll
    for (int p = 0; p < 9; ++p) sx1[(bb * 16 + c) * 9 + p] = fmaxf(acc[p], 0.0f);
    __syncthreads();

    float a2[2][4];
#pragma unroll
    for (int q = 0; q < 2; ++q) {
        float bcc = b2[c + 16 * q];
#pragma unroll
        for (int p = 0; p < 4; ++p) a2[q][p] = bcc;
    }
    for (int ci = 0; ci < 16; ++ci) {
        float xv[9];
#pragma unroll
        for (int p = 0; p < 9; ++p) xv[p] = sx1[(bb * 16 + ci) * 9 + p];
#pragma unroll
        for (int q = 0; q < 2; ++q) {
            int c2 = c + 16 * q;
#pragma unroll
            for (int ky = 0; ky < 2; ++ky)
#pragma unroll
                for (int kx = 0; kx < 2; ++kx) {
                    float w = sw2[(c2 * 16 + ci) * 4 + ky * 2 + kx];
#pragma unroll
                    for (int i = 0; i < 2; ++i)
#pragma unroll
                        for (int jx = 0; jx < 2; ++jx)
                            a2[q][i*2+jx] = fmaf(xv[(i+ky)*3 + (jx+kx)], w, a2[q][i*2+jx]);
                }
        }
    }
    float* outp = g_x2 + (size_t)(b0 + bb) * 128;
#pragma unroll
    for (int q = 0; q < 2; ++q)
#pragma unroll
        for (int p = 0; p < 4; ++p)
            outp[(c + 16 * q) * 4 + p] = fmaxf(a2[q][p], 0.0f);
}

__global__ void fc_k(const float* __restrict__ W, const float* __restrict__ bias)
{
    int gid = blockIdx.x * 256 + threadIdx.x;
    int b = gid >> 7, jj = gid & 127;
    const float* xr = g_x2 + (size_t)b * 128;
    const float* wr = W + (size_t)jj * 128;
    float acc = bias[jj];
#pragma unroll 8
    for (int k = 0; k < 128; ++k) acc = fmaf(xr[k], wr[k], acc);
    g_zc[gid] = fmaxf(acc, 0.0f);
}

extern "C" void kernel_launch(void* const* d_in, const int* in_sizes, int n_in,
                              void* d_out, int out_size)
{
    const float* cnn  = (const float*)d_in[0];
    const float* lin  = (const float*)d_in[1];
    const float* c1w  = (const float*)d_in[2];
    const float* c1b  = (const float*)d_in[3];
    const float* c2w  = (const float*)d_in[4];
    const float* c2b  = (const float*)d_in[5];
    const float* fcw  = (const float*)d_in[6];
    const float* fcb  = (const float*)d_in[7];
    const float* eWih = (const float*)d_in[8];
    const float* eWhh = (const float*)d_in[9];
    const float* ebih = (const float*)d_in[10];
    const float* ebhh = (const float*)d_in[11];
    const float* dWih = (const float*)d_in[12];
    const float* dWhh = (const float*)d_in[13];
    const float* dbih = (const float*)d_in[14];
    const float* dbhh = (const float*)d_in[15];
    const float* disw = (const float*)d_in[16];
    const float* disb = (const float*)d_in[17];
    const float* vw   = (const float*)d_in[18];
    const float* vb   = (const float*)d_in[19];
    float* out = (float*)d_out;

    cudaFuncSetAttribute(conv_k,  cudaFuncAttributeMaxDynamicSharedMemorySize, CONV_SMEM);
    cudaFuncSetAttribute(recur_k, cudaFuncAttributeMaxDynamicSharedMemorySize, SMEM_BYTES);

    wt_k<<<(128*384 + 128*768 + 255) / 256, 256>>>(eWhh, dWih, dWhh);
    conv_k<<<BATCH / 8, 128, CONV_SMEM>>>(cnn, c1w, c1b, c2w, c2b);
    fc_k<<<BATCH * 128 / 256, 256>>>(fcw, fcb);

    recur_k<<<NCTA, THREADS, SMEM_BYTES>>>(lin, eWih,
                                           ebih, ebhh, dbih, dbhh,
                                           disw, disb, vw, vb, out);
}